// round 2
// baseline (speedup 1.0000x reference)
#include <cuda_runtime.h>
#include <cuda_bf16.h>
#include <math.h>

// ---------------- problem constants ----------------
#define CB 8       // batch
#define CT 128     // time
#define CE 512     // embed dim
#define CH 1024    // hidden
#define CM 512     // mem hidden
#define CM2 1024   // 2*M
#define CS 16
#define CU 128
#define CW 1024
#define CV 32000
#define C3H 3072
#define CF 2048    // H + 2M (feature dim into output proj)

// ---------------- scratch (device globals; no runtime alloc) ----------------
__device__ float g_emb[CB * CT * CE];          // 2 MB
__device__ float g_gi[CB * CT * C3H];          // 12.6 MB (reused for both layers)
__device__ float g_h1[CB * CT * CH];           // 4 MB
__device__ float g_rnn[CB * CT * CH];          // 4 MB
__device__ float g_hbuf[2 * CB * CH];          // GRU state double buffer
__device__ float g_proj_s[CB * CS * CH];
__device__ float g_proj_u[CB * CU * CH];
__device__ float g_proj_w[CB * CW * CH];       // 33.5 MB
__device__ float g_sc_s[CB * CT * CS];
__device__ float g_sc_u[CB * CT * CU];
__device__ float g_sc_w[CB * CT * CW];
__device__ float g_suw[CB * CT * CW];          // 4 MB
__device__ float g_wT[CB * CM2 * CW];          // 33.5 MB  (w_output transposed per batch)
__device__ float g_feat[CB * CT * CF];         // 8.4 MB
__device__ unsigned g_bar_arr = 0;
__device__ unsigned g_bar_gen = 0;

// ---------------- grid barrier (persistent GRU kernel) ----------------
__device__ __forceinline__ void grid_sync_all(unsigned nb) {
    __threadfence();
    __syncthreads();
    if (threadIdx.x == 0) {
        unsigned gen = atomicAdd(&g_bar_gen, 0u);
        if (atomicAdd(&g_bar_arr, 1u) == nb - 1u) {
            atomicExch(&g_bar_arr, 0u);
            __threadfence();
            atomicAdd(&g_bar_gen, 1u);
        } else {
            while (atomicAdd(&g_bar_gen, 0u) == gen) { __nanosleep(64); }
        }
    }
    __syncthreads();
}

// ---------------- block reductions (256 threads fixed) ----------------
__device__ __forceinline__ float blockReduceMax256(float v, float* red) {
    #pragma unroll
    for (int o = 16; o; o >>= 1) v = fmaxf(v, __shfl_xor_sync(0xffffffffu, v, o));
    if ((threadIdx.x & 31) == 0) red[threadIdx.x >> 5] = v;
    __syncthreads();
    if (threadIdx.x < 32) {
        float r = (threadIdx.x < 8) ? red[threadIdx.x] : -INFINITY;
        #pragma unroll
        for (int o = 4; o; o >>= 1) r = fmaxf(r, __shfl_xor_sync(0xffffffffu, r, o));
        if (threadIdx.x == 0) red[0] = r;
    }
    __syncthreads();
    float out = red[0];
    __syncthreads();
    return out;
}

__device__ __forceinline__ float blockReduceSum256(float v, float* red) {
    #pragma unroll
    for (int o = 16; o; o >>= 1) v += __shfl_xor_sync(0xffffffffu, v, o);
    if ((threadIdx.x & 31) == 0) red[threadIdx.x >> 5] = v;
    __syncthreads();
    if (threadIdx.x < 32) {
        float r = (threadIdx.x < 8) ? red[threadIdx.x] : 0.f;
        #pragma unroll
        for (int o = 4; o; o >>= 1) r += __shfl_xor_sync(0xffffffffu, r, o);
        if (threadIdx.x == 0) red[0] = r;
    }
    __syncthreads();
    float out = red[0];
    __syncthreads();
    return out;
}

// ---------------- embedding gather ----------------
__global__ void embed_kernel(const int* __restrict__ target, const float* __restrict__ emb) {
    int i = blockIdx.x * blockDim.x + threadIdx.x;
    if (i < CB * CT * CE) {
        int bt = i / CE, e = i - bt * CE;
        g_emb[i] = emb[(size_t)target[bt] * CE + e];
    }
}

// ---------------- generic NT GEMM: C[m,n] = A[m,:] . B[n,:] + bias[n] ----------------
// Requires M%128==0, N%128==0, K%8==0 (all call sites satisfy this).
__global__ __launch_bounds__(256) void sgemm_nt(
    const float* __restrict__ A, const float* __restrict__ Bm,
    const float* __restrict__ bias, float* __restrict__ C,
    int M, int N, int K, int ldc,
    long sA, long sB, long sC)
{
    __shared__ float As[8][128];
    __shared__ float Bs[8][128];
    const float* Ab = A + (size_t)blockIdx.z * sA;
    const float* Bb = Bm + (size_t)blockIdx.z * sB;
    float* Cb = C + (size_t)blockIdx.z * sC;
    int n0 = blockIdx.x * 128, m0 = blockIdx.y * 128;
    int tid = threadIdx.x;
    int arow = tid >> 1, acol = (tid & 1) * 4;
    int ty = tid >> 4, tx = tid & 15;
    float acc[8][8];
    #pragma unroll
    for (int i = 0; i < 8; i++)
        #pragma unroll
        for (int j = 0; j < 8; j++) acc[i][j] = 0.f;

    for (int k0 = 0; k0 < K; k0 += 8) {
        float4 av = *(const float4*)(Ab + (size_t)(m0 + arow) * K + k0 + acol);
        float4 bv = *(const float4*)(Bb + (size_t)(n0 + arow) * K + k0 + acol);
        As[acol + 0][arow] = av.x; As[acol + 1][arow] = av.y;
        As[acol + 2][arow] = av.z; As[acol + 3][arow] = av.w;
        Bs[acol + 0][arow] = bv.x; Bs[acol + 1][arow] = bv.y;
        Bs[acol + 2][arow] = bv.z; Bs[acol + 3][arow] = bv.w;
        __syncthreads();
        #pragma unroll
        for (int kk = 0; kk < 8; kk++) {
            float a[8], b[8];
            #pragma unroll
            for (int i = 0; i < 8; i++) a[i] = As[kk][ty * 8 + i];
            #pragma unroll
            for (int j = 0; j < 8; j++) b[j] = Bs[kk][tx * 8 + j];
            #pragma unroll
            for (int i = 0; i < 8; i++)
                #pragma unroll
                for (int j = 0; j < 8; j++) acc[i][j] += a[i] * b[j];
        }
        __syncthreads();
    }
    #pragma unroll
    for (int i = 0; i < 8; i++) {
        int m = m0 + ty * 8 + i;
        #pragma unroll
        for (int j = 0; j < 8; j++) {
            int n = n0 + tx * 8 + j;
            float v = acc[i][j] + (bias ? bias[n] : 0.f);
            Cb[(size_t)m * ldc + n] = v;
        }
    }
}

// ---------------- persistent GRU layer ----------------
// gi: [B*T, 3H] precomputed x@Wi^T + bi ; Wh: [3H, H]; bh: [3H]; hout: [B,T,H]
__global__ __launch_bounds__(256) void gru_layer_kernel(
    const float* __restrict__ gi, const float* __restrict__ Wh,
    const float* __restrict__ bh, float* __restrict__ hout)
{
    __shared__ float h_s[CB * CH];   // 32 KB
    int tid = threadIdx.x;
    // zero hidden state (both buffers)
    for (int i = tid + blockIdx.x * 256; i < 2 * CB * CH; i += gridDim.x * 256)
        g_hbuf[i] = 0.f;
    grid_sync_all(gridDim.x);

    int warp = tid >> 5, lane = tid & 31;
    int j = blockIdx.x * 8 + warp;                 // this warp's hidden unit
    float bhr = bh[0 * CH + j], bhz = bh[1 * CH + j], bhn = bh[2 * CH + j];
    const float* Wr = Wh + (size_t)(0 * CH + j) * CH;
    const float* Wz = Wh + (size_t)(1 * CH + j) * CH;
    const float* Wn = Wh + (size_t)(2 * CH + j) * CH;

    for (int t = 0; t < CT; t++) {
        int cur = t & 1;
        const float* hsrc = g_hbuf + cur * CB * CH;
        for (int i = tid; i < CB * CH / 4; i += 256)
            ((float4*)h_s)[i] = ((const float4*)hsrc)[i];
        __syncthreads();

        float accr[CB], accz[CB], accn[CB];
        #pragma unroll
        for (int b = 0; b < CB; b++) { accr[b] = 0.f; accz[b] = 0.f; accn[b] = 0.f; }
        for (int k = lane * 4; k < CH; k += 128) {
            float4 wr = *(const float4*)(Wr + k);
            float4 wz = *(const float4*)(Wz + k);
            float4 wn = *(const float4*)(Wn + k);
            #pragma unroll
            for (int b = 0; b < CB; b++) {
                float4 hv = *(const float4*)(h_s + b * CH + k);
                accr[b] += wr.x * hv.x + wr.y * hv.y + wr.z * hv.z + wr.w * hv.w;
                accz[b] += wz.x * hv.x + wz.y * hv.y + wz.z * hv.z + wz.w * hv.w;
                accn[b] += wn.x * hv.x + wn.y * hv.y + wn.z * hv.z + wn.w * hv.w;
            }
        }
        #pragma unroll
        for (int b = 0; b < CB; b++) {
            #pragma unroll
            for (int o = 16; o; o >>= 1) {
                accr[b] += __shfl_xor_sync(0xffffffffu, accr[b], o);
                accz[b] += __shfl_xor_sync(0xffffffffu, accz[b], o);
                accn[b] += __shfl_xor_sync(0xffffffffu, accn[b], o);
            }
        }
        if (lane == 0) {
            #pragma unroll
            for (int b = 0; b < CB; b++) {
                const float* gib = gi + (size_t)(b * CT + t) * C3H;
                float ir = gib[0 * CH + j], iz = gib[1 * CH + j], inn = gib[2 * CH + j];
                float hprev = h_s[b * CH + j];
                float r = 1.f / (1.f + expf(-(ir + accr[b] + bhr)));
                float z = 1.f / (1.f + expf(-(iz + accz[b] + bhz)));
                float n = tanhf(inn + r * (accn[b] + bhn));
                float hn = (1.f - z) * n + z * hprev;
                g_hbuf[(cur ^ 1) * CB * CH + b * CH + j] = hn;
                hout[(size_t)(b * CT + t) * CH + j] = hn;
            }
        }
        grid_sync_all(gridDim.x);
    }
}

// ---------------- small attention scores (one warp per dot), N in {16,128} ----------------
__global__ void attn_scores_kernel(const float* __restrict__ q, const float* __restrict__ proj,
                                   float* __restrict__ out, int N) {
    int gw = (blockIdx.x * blockDim.x + threadIdx.x) >> 5;
    int lane = threadIdx.x & 31;
    if (gw >= CB * CT * N) return;
    int n = gw % N;
    int bt = gw / N;
    int b = bt / CT;
    const float* qp = q + (size_t)bt * CH;
    const float* pp = proj + (size_t)(b * N + n) * CH;
    float acc = 0.f;
    for (int k = lane * 4; k < CH; k += 128) {
        float4 qa = *(const float4*)(qp + k);
        float4 pa = *(const float4*)(pp + k);
        acc += qa.x * pa.x + qa.y * pa.y + qa.z * pa.z + qa.w * pa.w;
    }
    #pragma unroll
    for (int o = 16; o; o >>= 1) acc += __shfl_xor_sync(0xffffffffu, acc, o);
    if (lane == 0) out[gw] = acc;
}

// ---------------- fused masked softmaxes + hierarchical combine + final softmax ----------------
__global__ __launch_bounds__(256) void combine_kernel(
    const int* __restrict__ s_len, const int* __restrict__ u_len, const int* __restrict__ w_len,
    const int* __restrict__ seg, const int* __restrict__ utt)
{
    int bt = blockIdx.x, b = bt / CT, tid = threadIdx.x;
    __shared__ float ss[CS];
    __shared__ float su[CU];
    __shared__ float sw[CW];
    __shared__ float red[32];
    int sl = s_len[b], ul = u_len[b], wl = w_len[b];

    // segment softmax (warp 0)
    if (tid < 32) {
        float v = (tid < sl) ? g_sc_s[bt * CS + tid] : -INFINITY;
        float m = v;
        #pragma unroll
        for (int o = 16; o; o >>= 1) m = fmaxf(m, __shfl_xor_sync(0xffffffffu, m, o));
        float e = (tid < sl) ? expf(v - m) : 0.f;
        float s = e;
        #pragma unroll
        for (int o = 16; o; o >>= 1) s += __shfl_xor_sync(0xffffffffu, s, o);
        if (tid < CS) ss[tid] = e / s;
    }
    // utterance softmax
    float uv = (tid < CU && tid < ul) ? g_sc_u[bt * CU + tid] : -INFINITY;
    float um = blockReduceMax256(uv, red);
    float ue = (tid < CU && tid < ul) ? expf(uv - um) : 0.f;
    float us = blockReduceSum256(ue, red);
    if (tid < CU) su[tid] = ue / us;
    // word softmax
    float wv[4], we[4];
    float wm = -INFINITY;
    #pragma unroll
    for (int i = 0; i < 4; i++) {
        int idx = tid + 256 * i;
        wv[i] = (idx < wl) ? g_sc_w[(size_t)bt * CW + idx] : -INFINITY;
        wm = fmaxf(wm, wv[i]);
    }
    wm = blockReduceMax256(wm, red);
    float wsum = 0.f;
    #pragma unroll
    for (int i = 0; i < 4; i++) {
        int idx = tid + 256 * i;
        we[i] = (idx < wl) ? expf(wv[i] - wm) : 0.f;
        wsum += we[i];
    }
    wsum = blockReduceSum256(wsum, red);
    #pragma unroll
    for (int i = 0; i < 4; i++) sw[tid + 256 * i] = we[i] / wsum;
    __syncthreads();
    // seg->utt product
    if (tid < CU) {
        float v2 = (tid < ul) ? ss[seg[b * CU + tid]] * su[tid] : 0.f;
        su[tid] = v2;
    }
    __syncthreads();
    // utt->word product (zeros for invalid), then softmax over FULL W axis
    float pv[4];
    #pragma unroll
    for (int i = 0; i < 4; i++) {
        int idx = tid + 256 * i;
        pv[i] = (idx < wl) ? su[utt[b * CW + idx]] * sw[idx] : 0.f;
    }
    float pm = fmaxf(fmaxf(pv[0], pv[1]), fmaxf(pv[2], pv[3]));
    pm = blockReduceMax256(pm, red);
    float pe[4];
    float psum = 0.f;
    #pragma unroll
    for (int i = 0; i < 4; i++) { pe[i] = expf(pv[i] - pm); psum += pe[i]; }
    psum = blockReduceSum256(psum, red);
    #pragma unroll
    for (int i = 0; i < 4; i++)
        g_suw[(size_t)bt * CW + tid + 256 * i] = pe[i] / psum;
}

// ---------------- per-batch transpose of w_output: [B,W,2M] -> [B,2M,W] ----------------
__global__ void transpose_w_kernel(const float* __restrict__ wo) {
    __shared__ float tile[32][33];
    int b = blockIdx.z;
    int w0 = blockIdx.x * 32, m0 = blockIdx.y * 32;
    int x = threadIdx.x, y = threadIdx.y;
    #pragma unroll
    for (int i = 0; i < 32; i += 8)
        tile[y + i][x] = wo[((size_t)b * CW + (w0 + y + i)) * CM2 + m0 + x];
    __syncthreads();
    #pragma unroll
    for (int i = 0; i < 32; i += 8)
        g_wT[((size_t)b * CM2 + (m0 + y + i)) * CW + w0 + x] = tile[x][y + i];
}

// ---------------- copy rnn_out into second half of feature matrix ----------------
__global__ void copy_rnn_kernel() {
    int i = blockIdx.x * blockDim.x + threadIdx.x;
    if (i < CB * CT * CH) {
        int bt = i / CH, j = i - bt * CH;
        g_feat[(size_t)bt * CF + CM2 + j] = g_rnn[i];
    }
}

// ---------------- in-place log_softmax over V per (b,t) row ----------------
__global__ __launch_bounds__(256) void logsoftmax_kernel(float* __restrict__ out) {
    __shared__ float red[32];
    int row = blockIdx.x, tid = threadIdx.x;
    float* p = out + (size_t)row * CV;
    float m = -INFINITY;
    for (int i = tid; i < CV; i += 256) m = fmaxf(m, p[i]);
    m = blockReduceMax256(m, red);
    float s = 0.f;
    for (int i = tid; i < CV; i += 256) s += expf(p[i] - m);
    s = blockReduceSum256(s, red);
    float lse = m + logf(s);
    for (int i = tid; i < CV; i += 256) p[i] -= lse;
}

// ---------------- launch ----------------
extern "C" void kernel_launch(void* const* d_in, const int* in_sizes, int n_in,
                              void* d_out, int out_size) {
    const int*   target   = (const int*)d_in[0];
    const float* embedding= (const float*)d_in[1];
    const float* W_ih0    = (const float*)d_in[2];
    const float* W_hh0    = (const float*)d_in[3];
    const float* b_ih0    = (const float*)d_in[4];
    const float* b_hh0    = (const float*)d_in[5];
    const float* W_ih1    = (const float*)d_in[6];
    const float* W_hh1    = (const float*)d_in[7];
    const float* b_ih1    = (const float*)d_in[8];
    const float* b_hh1    = (const float*)d_in[9];
    const float* att_s_w  = (const float*)d_in[10];
    const float* att_s_b  = (const float*)d_in[11];
    const float* att_u_w  = (const float*)d_in[12];
    const float* att_u_b  = (const float*)d_in[13];
    const float* att_w_w  = (const float*)d_in[14];
    const float* att_w_b  = (const float*)d_in[15];
    const float* out_w    = (const float*)d_in[16];
    const float* out_b    = (const float*)d_in[17];
    const float* s_output = (const float*)d_in[18];
    const float* u_output = (const float*)d_in[19];
    const float* w_output = (const float*)d_in[20];
    const int*   s_len    = (const int*)d_in[21];
    const int*   u_len    = (const int*)d_in[22];
    const int*   w_len    = (const int*)d_in[23];
    const int*   seg      = (const int*)d_in[24];
    const int*   utt      = (const int*)d_in[25];
    float* out = (float*)d_out;

    float *p_emb, *p_gi, *p_h1, *p_rnn, *p_ps, *p_pu, *p_pw, *p_scs, *p_scu, *p_scw, *p_suw, *p_wT, *p_feat;
    cudaGetSymbolAddress((void**)&p_emb, g_emb);
    cudaGetSymbolAddress((void**)&p_gi, g_gi);
    cudaGetSymbolAddress((void**)&p_h1, g_h1);
    cudaGetSymbolAddress((void**)&p_rnn, g_rnn);
    cudaGetSymbolAddress((void**)&p_ps, g_proj_s);
    cudaGetSymbolAddress((void**)&p_pu, g_proj_u);
    cudaGetSymbolAddress((void**)&p_pw, g_proj_w);
    cudaGetSymbolAddress((void**)&p_scs, g_sc_s);
    cudaGetSymbolAddress((void**)&p_scu, g_sc_u);
    cudaGetSymbolAddress((void**)&p_scw, g_sc_w);
    cudaGetSymbolAddress((void**)&p_suw, g_suw);
    cudaGetSymbolAddress((void**)&p_wT, g_wT);
    cudaGetSymbolAddress((void**)&p_feat, g_feat);

    // 1. embedding gather
    embed_kernel<<<(CB * CT * CE + 255) / 256, 256>>>(target, embedding);
    // 2. gi0 = emb @ W_ih0^T + b_ih0   [1024, 3072], K=512
    sgemm_nt<<<dim3(C3H / 128, (CB * CT) / 128, 1), 256>>>(p_emb, W_ih0, b_ih0, p_gi,
        CB * CT, C3H, CE, C3H, 0, 0, 0);
    // 3. GRU layer 0 (persistent)
    gru_layer_kernel<<<128, 256>>>(p_gi, W_hh0, b_hh0, p_h1);
    // 4. gi1 = h1 @ W_ih1^T + b_ih1    [1024, 3072], K=1024
    sgemm_nt<<<dim3(C3H / 128, (CB * CT) / 128, 1), 256>>>(p_h1, W_ih1, b_ih1, p_gi,
        CB * CT, C3H, CH, C3H, 0, 0, 0);
    // 5. GRU layer 1
    gru_layer_kernel<<<128, 256>>>(p_gi, W_hh1, b_hh1, p_rnn);
    // 6. attention memory projections
    sgemm_nt<<<dim3(CH / 128, (CB * CS) / 128, 1), 256>>>(s_output, att_s_w, att_s_b, p_ps,
        CB * CS, CH, CM, CH, 0, 0, 0);
    sgemm_nt<<<dim3(CH / 128, (CB * CU) / 128, 1), 256>>>(u_output, att_u_w, att_u_b, p_pu,
        CB * CU, CH, CM, CH, 0, 0, 0);
    sgemm_nt<<<dim3(CH / 128, (CB * CW) / 128, 1), 256>>>(w_output, att_w_w, att_w_b, p_pw,
        CB * CW, CH, CM2, CH, 0, 0, 0);
    // 7. raw scores
    attn_scores_kernel<<<(CB * CT * CS) / 8, 256>>>(p_rnn, p_ps, p_scs, CS);
    attn_scores_kernel<<<(CB * CT * CU) / 8, 256>>>(p_rnn, p_pu, p_scu, CU);
    sgemm_nt<<<dim3(CW / 128, CT / 128, CB), 256>>>(p_rnn, p_pw, nullptr, p_scw,
        CT, CW, CH, CW, (long)CT * CH, (long)CW * CH, (long)CT * CW);
    // 8. masked softmaxes + hierarchical combine + final softmax
    combine_kernel<<<CB * CT, 256>>>(s_len, u_len, w_len, seg, utt);
    // 9. context = suw @ w_output  (needs w_output^T per batch for NT gemm)
    transpose_w_kernel<<<dim3(CW / 32, CM2 / 32, CB), dim3(32, 8)>>>(w_output);
    sgemm_nt<<<dim3(CM2 / 128, CT / 128, CB), 256>>>(p_suw, p_wT, nullptr, p_feat,
        CT, CM2, CW, CF, (long)CT * CW, (long)CM2 * CW, (long)CT * CF);
    // 10. feat[:, 1024:2048] = rnn_out
    copy_rnn_kernel<<<(CB * CT * CH + 255) / 256, 256>>>();
    // 11. logits = feat @ out_w^T + out_b  -> d_out   [1024, 32000], K=2048
    sgemm_nt<<<dim3(CV / 128, (CB * CT) / 128, 1), 256>>>(p_feat, out_w, out_b, out,
        CB * CT, CV, CF, CV, 0, 0, 0);
    // 12. in-place log_softmax
    logsoftmax_kernel<<<CB * CT, 256>>>(out);
}

// round 3
// speedup vs baseline: 1.0014x; 1.0014x over previous
#include <cuda_runtime.h>
#include <cuda_bf16.h>
#include <math.h>

// ---------------- problem constants ----------------
#define CB 8       // batch
#define CT 128     // time
#define CE 512     // embed dim
#define CH 1024    // hidden
#define CM 512     // mem hidden
#define CM2 1024   // 2*M
#define CS 16
#define CU 128
#define CW 1024
#define CV 32000
#define C3H 3072
#define CF 2048    // H + 2M (feature dim into output proj)

// ---------------- scratch (device globals; no runtime alloc) ----------------
__device__ float g_emb[CB * CT * CE];          // 2 MB
__device__ float g_gi[CB * CT * C3H];          // 12.6 MB (reused for both layers)
__device__ float g_h1[CB * CT * CH];           // 4 MB
__device__ float g_rnn[CB * CT * CH];          // 4 MB
__device__ float g_hbuf[2 * CB * CH];          // GRU state double buffer
__device__ float g_proj_s[CB * CS * CH];
__device__ float g_proj_u[CB * CU * CH];
__device__ float g_proj_w[CB * CW * CH];       // 33.5 MB
__device__ float g_sc_s[CB * CT * CS];
__device__ float g_sc_u[CB * CT * CU];
__device__ float g_sc_w[CB * CT * CW];
__device__ float g_suw[CB * CT * CW];          // 4 MB
__device__ float g_wT[CB * CM2 * CW];          // 33.5 MB  (w_output transposed per batch)
__device__ float g_feat[CB * CT * CF];         // 8.4 MB
__device__ unsigned g_bar_arr = 0;
__device__ unsigned g_bar_gen = 0;

// ---------------- grid barrier (persistent GRU kernel) ----------------
__device__ __forceinline__ void grid_sync_all(unsigned nb) {
    __threadfence();
    __syncthreads();
    if (threadIdx.x == 0) {
        unsigned gen = atomicAdd(&g_bar_gen, 0u);
        if (atomicAdd(&g_bar_arr, 1u) == nb - 1u) {
            atomicExch(&g_bar_arr, 0u);
            __threadfence();
            atomicAdd(&g_bar_gen, 1u);
        } else {
            while (atomicAdd(&g_bar_gen, 0u) == gen) { __nanosleep(64); }
        }
    }
    __syncthreads();
}

// ---------------- block reductions (256 threads fixed) ----------------
__device__ __forceinline__ float blockReduceMax256(float v, float* red) {
    #pragma unroll
    for (int o = 16; o; o >>= 1) v = fmaxf(v, __shfl_xor_sync(0xffffffffu, v, o));
    if ((threadIdx.x & 31) == 0) red[threadIdx.x >> 5] = v;
    __syncthreads();
    if (threadIdx.x < 32) {
        float r = (threadIdx.x < 8) ? red[threadIdx.x] : -INFINITY;
        #pragma unroll
        for (int o = 4; o; o >>= 1) r = fmaxf(r, __shfl_xor_sync(0xffffffffu, r, o));
        if (threadIdx.x == 0) red[0] = r;
    }
    __syncthreads();
    float out = red[0];
    __syncthreads();
    return out;
}

__device__ __forceinline__ float blockReduceSum256(float v, float* red) {
    #pragma unroll
    for (int o = 16; o; o >>= 1) v += __shfl_xor_sync(0xffffffffu, v, o);
    if ((threadIdx.x & 31) == 0) red[threadIdx.x >> 5] = v;
    __syncthreads();
    if (threadIdx.x < 32) {
        float r = (threadIdx.x < 8) ? red[threadIdx.x] : 0.f;
        #pragma unroll
        for (int o = 4; o; o >>= 1) r += __shfl_xor_sync(0xffffffffu, r, o);
        if (threadIdx.x == 0) red[0] = r;
    }
    __syncthreads();
    float out = red[0];
    __syncthreads();
    return out;
}

// ---------------- embedding gather ----------------
__global__ void embed_kernel(const int* __restrict__ target, const float* __restrict__ emb) {
    int i = blockIdx.x * blockDim.x + threadIdx.x;
    if (i < CB * CT * CE) {
        int bt = i / CE, e = i - bt * CE;
        g_emb[i] = emb[(size_t)target[bt] * CE + e];
    }
}

// ---------------- generic NT GEMM: C[m,n] = A[m,:] . B[n,:] + bias[n] ----------------
// Requires M%128==0, N%128==0, K%8==0 (all call sites satisfy this).
__global__ __launch_bounds__(256) void sgemm_nt(
    const float* __restrict__ A, const float* __restrict__ Bm,
    const float* __restrict__ bias, float* __restrict__ C,
    int M, int N, int K, int ldc,
    long sA, long sB, long sC)
{
    __shared__ float As[8][128];
    __shared__ float Bs[8][128];
    const float* Ab = A + (size_t)blockIdx.z * sA;
    const float* Bb = Bm + (size_t)blockIdx.z * sB;
    float* Cb = C + (size_t)blockIdx.z * sC;
    int n0 = blockIdx.x * 128, m0 = blockIdx.y * 128;
    int tid = threadIdx.x;
    int arow = tid >> 1, acol = (tid & 1) * 4;
    int ty = tid >> 4, tx = tid & 15;
    float acc[8][8];
    #pragma unroll
    for (int i = 0; i < 8; i++)
        #pragma unroll
        for (int j = 0; j < 8; j++) acc[i][j] = 0.f;

    for (int k0 = 0; k0 < K; k0 += 8) {
        float4 av = *(const float4*)(Ab + (size_t)(m0 + arow) * K + k0 + acol);
        float4 bv = *(const float4*)(Bb + (size_t)(n0 + arow) * K + k0 + acol);
        As[acol + 0][arow] = av.x; As[acol + 1][arow] = av.y;
        As[acol + 2][arow] = av.z; As[acol + 3][arow] = av.w;
        Bs[acol + 0][arow] = bv.x; Bs[acol + 1][arow] = bv.y;
        Bs[acol + 2][arow] = bv.z; Bs[acol + 3][arow] = bv.w;
        __syncthreads();
        #pragma unroll
        for (int kk = 0; kk < 8; kk++) {
            float a[8], b[8];
            #pragma unroll
            for (int i = 0; i < 8; i++) a[i] = As[kk][ty * 8 + i];
            #pragma unroll
            for (int j = 0; j < 8; j++) b[j] = Bs[kk][tx * 8 + j];
            #pragma unroll
            for (int i = 0; i < 8; i++)
                #pragma unroll
                for (int j = 0; j < 8; j++) acc[i][j] += a[i] * b[j];
        }
        __syncthreads();
    }
    #pragma unroll
    for (int i = 0; i < 8; i++) {
        int m = m0 + ty * 8 + i;
        #pragma unroll
        for (int j = 0; j < 8; j++) {
            int n = n0 + tx * 8 + j;
            float v = acc[i][j] + (bias ? bias[n] : 0.f);
            Cb[(size_t)m * ldc + n] = v;
        }
    }
}

// ---------------- persistent GRU layer ----------------
// gi: [B*T, 3H] precomputed x@Wi^T + bi ; Wh: [3H, H]; bh: [3H]; hout: [B,T,H]
__global__ __launch_bounds__(256) void gru_layer_kernel(
    const float* __restrict__ gi, const float* __restrict__ Wh,
    const float* __restrict__ bh, float* __restrict__ hout)
{
    __shared__ float h_s[CB * CH];   // 32 KB
    int tid = threadIdx.x;
    // zero hidden state (both buffers)
    for (int i = tid + blockIdx.x * 256; i < 2 * CB * CH; i += gridDim.x * 256)
        g_hbuf[i] = 0.f;
    grid_sync_all(gridDim.x);

    int warp = tid >> 5, lane = tid & 31;
    int j = blockIdx.x * 8 + warp;                 // this warp's hidden unit
    float bhr = bh[0 * CH + j], bhz = bh[1 * CH + j], bhn = bh[2 * CH + j];
    const float* Wr = Wh + (size_t)(0 * CH + j) * CH;
    const float* Wz = Wh + (size_t)(1 * CH + j) * CH;
    const float* Wn = Wh + (size_t)(2 * CH + j) * CH;

    for (int t = 0; t < CT; t++) {
        int cur = t & 1;
        const float* hsrc = g_hbuf + cur * CB * CH;
        for (int i = tid; i < CB * CH / 4; i += 256)
            ((float4*)h_s)[i] = ((const float4*)hsrc)[i];
        __syncthreads();

        float accr[CB], accz[CB], accn[CB];
        #pragma unroll
        for (int b = 0; b < CB; b++) { accr[b] = 0.f; accz[b] = 0.f; accn[b] = 0.f; }
        for (int k = lane * 4; k < CH; k += 128) {
            float4 wr = *(const float4*)(Wr + k);
            float4 wz = *(const float4*)(Wz + k);
            float4 wn = *(const float4*)(Wn + k);
            #pragma unroll
            for (int b = 0; b < CB; b++) {
                float4 hv = *(const float4*)(h_s + b * CH + k);
                accr[b] += wr.x * hv.x + wr.y * hv.y + wr.z * hv.z + wr.w * hv.w;
                accz[b] += wz.x * hv.x + wz.y * hv.y + wz.z * hv.z + wz.w * hv.w;
                accn[b] += wn.x * hv.x + wn.y * hv.y + wn.z * hv.z + wn.w * hv.w;
            }
        }
        #pragma unroll
        for (int b = 0; b < CB; b++) {
            #pragma unroll
            for (int o = 16; o; o >>= 1) {
                accr[b] += __shfl_xor_sync(0xffffffffu, accr[b], o);
                accz[b] += __shfl_xor_sync(0xffffffffu, accz[b], o);
                accn[b] += __shfl_xor_sync(0xffffffffu, accn[b], o);
            }
        }
        if (lane == 0) {
            #pragma unroll
            for (int b = 0; b < CB; b++) {
                const float* gib = gi + (size_t)(b * CT + t) * C3H;
                float ir = gib[0 * CH + j], iz = gib[1 * CH + j], inn = gib[2 * CH + j];
                float hprev = h_s[b * CH + j];
                float r = 1.f / (1.f + expf(-(ir + accr[b] + bhr)));
                float z = 1.f / (1.f + expf(-(iz + accz[b] + bhz)));
                float n = tanhf(inn + r * (accn[b] + bhn));
                float hn = (1.f - z) * n + z * hprev;
                g_hbuf[(cur ^ 1) * CB * CH + b * CH + j] = hn;
                hout[(size_t)(b * CT + t) * CH + j] = hn;
            }
        }
        grid_sync_all(gridDim.x);
    }
}

// ---------------- small attention scores (one warp per dot), N in {16,128} ----------------
__global__ void attn_scores_kernel(const float* __restrict__ q, const float* __restrict__ proj,
                                   float* __restrict__ out, int N) {
    int gw = (blockIdx.x * blockDim.x + threadIdx.x) >> 5;
    int lane = threadIdx.x & 31;
    if (gw >= CB * CT * N) return;
    int n = gw % N;
    int bt = gw / N;
    int b = bt / CT;
    const float* qp = q + (size_t)bt * CH;
    const float* pp = proj + (size_t)(b * N + n) * CH;
    float acc = 0.f;
    for (int k = lane * 4; k < CH; k += 128) {
        float4 qa = *(const float4*)(qp + k);
        float4 pa = *(const float4*)(pp + k);
        acc += qa.x * pa.x + qa.y * pa.y + qa.z * pa.z + qa.w * pa.w;
    }
    #pragma unroll
    for (int o = 16; o; o >>= 1) acc += __shfl_xor_sync(0xffffffffu, acc, o);
    if (lane == 0) out[gw] = acc;
}

// ---------------- fused masked softmaxes + hierarchical combine + final softmax ----------------
__global__ __launch_bounds__(256) void combine_kernel(
    const int* __restrict__ s_len, const int* __restrict__ u_len, const int* __restrict__ w_len,
    const int* __restrict__ seg, const int* __restrict__ utt)
{
    int bt = blockIdx.x, b = bt / CT, tid = threadIdx.x;
    __shared__ float ss[CS];
    __shared__ float su[CU];
    __shared__ float sw[CW];
    __shared__ float red[32];
    int sl = s_len[b], ul = u_len[b], wl = w_len[b];

    // segment softmax (warp 0)
    if (tid < 32) {
        float v = (tid < sl) ? g_sc_s[bt * CS + tid] : -INFINITY;
        float m = v;
        #pragma unroll
        for (int o = 16; o; o >>= 1) m = fmaxf(m, __shfl_xor_sync(0xffffffffu, m, o));
        float e = (tid < sl) ? expf(v - m) : 0.f;
        float s = e;
        #pragma unroll
        for (int o = 16; o; o >>= 1) s += __shfl_xor_sync(0xffffffffu, s, o);
        if (tid < CS) ss[tid] = e / s;
    }
    // utterance softmax
    float uv = (tid < CU && tid < ul) ? g_sc_u[bt * CU + tid] : -INFINITY;
    float um = blockReduceMax256(uv, red);
    float ue = (tid < CU && tid < ul) ? expf(uv - um) : 0.f;
    float us = blockReduceSum256(ue, red);
    if (tid < CU) su[tid] = ue / us;
    // word softmax
    float wv[4], we[4];
    float wm = -INFINITY;
    #pragma unroll
    for (int i = 0; i < 4; i++) {
        int idx = tid + 256 * i;
        wv[i] = (idx < wl) ? g_sc_w[(size_t)bt * CW + idx] : -INFINITY;
        wm = fmaxf(wm, wv[i]);
    }
    wm = blockReduceMax256(wm, red);
    float wsum = 0.f;
    #pragma unroll
    for (int i = 0; i < 4; i++) {
        int idx = tid + 256 * i;
        we[i] = (idx < wl) ? expf(wv[i] - wm) : 0.f;
        wsum += we[i];
    }
    wsum = blockReduceSum256(wsum, red);
    #pragma unroll
    for (int i = 0; i < 4; i++) sw[tid + 256 * i] = we[i] / wsum;
    __syncthreads();
    // seg->utt product
    if (tid < CU) {
        float v2 = (tid < ul) ? ss[seg[b * CU + tid]] * su[tid] : 0.f;
        su[tid] = v2;
    }
    __syncthreads();
    // utt->word product (zeros for invalid), then softmax over FULL W axis
    float pv[4];
    #pragma unroll
    for (int i = 0; i < 4; i++) {
        int idx = tid + 256 * i;
        pv[i] = (idx < wl) ? su[utt[b * CW + idx]] * sw[idx] : 0.f;
    }
    float pm = fmaxf(fmaxf(pv[0], pv[1]), fmaxf(pv[2], pv[3]));
    pm = blockReduceMax256(pm, red);
    float pe[4];
    float psum = 0.f;
    #pragma unroll
    for (int i = 0; i < 4; i++) { pe[i] = expf(pv[i] - pm); psum += pe[i]; }
    psum = blockReduceSum256(psum, red);
    #pragma unroll
    for (int i = 0; i < 4; i++)
        g_suw[(size_t)bt * CW + tid + 256 * i] = pe[i] / psum;
}

// ---------------- per-batch transpose of w_output: [B,W,2M] -> [B,2M,W] ----------------
__global__ void transpose_w_kernel(const float* __restrict__ wo) {
    __shared__ float tile[32][33];
    int b = blockIdx.z;
    int w0 = blockIdx.x * 32, m0 = blockIdx.y * 32;
    int x = threadIdx.x, y = threadIdx.y;
    #pragma unroll
    for (int i = 0; i < 32; i += 8)
        tile[y + i][x] = wo[((size_t)b * CW + (w0 + y + i)) * CM2 + m0 + x];
    __syncthreads();
    #pragma unroll
    for (int i = 0; i < 32; i += 8)
        g_wT[((size_t)b * CM2 + (m0 + y + i)) * CW + w0 + x] = tile[x][y + i];
}

// ---------------- copy rnn_out into second half of feature matrix ----------------
__global__ void copy_rnn_kernel() {
    int i = blockIdx.x * blockDim.x + threadIdx.x;
    if (i < CB * CT * CH) {
        int bt = i / CH, j = i - bt * CH;
        g_feat[(size_t)bt * CF + CM2 + j] = g_rnn[i];
    }
}

// ---------------- in-place log_softmax over V per (b,t) row ----------------
__global__ __launch_bounds__(256) void logsoftmax_kernel(float* __restrict__ out) {
    __shared__ float red[32];
    int row = blockIdx.x, tid = threadIdx.x;
    float* p = out + (size_t)row * CV;
    float m = -INFINITY;
    for (int i = tid; i < CV; i += 256) m = fmaxf(m, p[i]);
    m = blockReduceMax256(m, red);
    float s = 0.f;
    for (int i = tid; i < CV; i += 256) s += expf(p[i] - m);
    s = blockReduceSum256(s, red);
    float lse = m + logf(s);
    for (int i = tid; i < CV; i += 256) p[i] -= lse;
}

// ---------------- launch ----------------
extern "C" void kernel_launch(void* const* d_in, const int* in_sizes, int n_in,
                              void* d_out, int out_size) {
    const int*   target   = (const int*)d_in[0];
    const float* embedding= (const float*)d_in[1];
    const float* W_ih0    = (const float*)d_in[2];
    const float* W_hh0    = (const float*)d_in[3];
    const float* b_ih0    = (const float*)d_in[4];
    const float* b_hh0    = (const float*)d_in[5];
    const float* W_ih1    = (const float*)d_in[6];
    const float* W_hh1    = (const float*)d_in[7];
    const float* b_ih1    = (const float*)d_in[8];
    const float* b_hh1    = (const float*)d_in[9];
    const float* att_s_w  = (const float*)d_in[10];
    const float* att_s_b  = (const float*)d_in[11];
    const float* att_u_w  = (const float*)d_in[12];
    const float* att_u_b  = (const float*)d_in[13];
    const float* att_w_w  = (const float*)d_in[14];
    const float* att_w_b  = (const float*)d_in[15];
    const float* out_w    = (const float*)d_in[16];
    const float* out_b    = (const float*)d_in[17];
    const float* s_output = (const float*)d_in[18];
    const float* u_output = (const float*)d_in[19];
    const float* w_output = (const float*)d_in[20];
    const int*   s_len    = (const int*)d_in[21];
    const int*   u_len    = (const int*)d_in[22];
    const int*   w_len    = (const int*)d_in[23];
    const int*   seg      = (const int*)d_in[24];
    const int*   utt      = (const int*)d_in[25];
    float* out = (float*)d_out;

    float *p_emb, *p_gi, *p_h1, *p_rnn, *p_ps, *p_pu, *p_pw, *p_scs, *p_scu, *p_scw, *p_suw, *p_wT, *p_feat;
    cudaGetSymbolAddress((void**)&p_emb, g_emb);
    cudaGetSymbolAddress((void**)&p_gi, g_gi);
    cudaGetSymbolAddress((void**)&p_h1, g_h1);
    cudaGetSymbolAddress((void**)&p_rnn, g_rnn);
    cudaGetSymbolAddress((void**)&p_ps, g_proj_s);
    cudaGetSymbolAddress((void**)&p_pu, g_proj_u);
    cudaGetSymbolAddress((void**)&p_pw, g_proj_w);
    cudaGetSymbolAddress((void**)&p_scs, g_sc_s);
    cudaGetSymbolAddress((void**)&p_scu, g_sc_u);
    cudaGetSymbolAddress((void**)&p_scw, g_sc_w);
    cudaGetSymbolAddress((void**)&p_suw, g_suw);
    cudaGetSymbolAddress((void**)&p_wT, g_wT);
    cudaGetSymbolAddress((void**)&p_feat, g_feat);

    // 1. embedding gather
    embed_kernel<<<(CB * CT * CE + 255) / 256, 256>>>(target, embedding);
    // 2. gi0 = emb @ W_ih0^T + b_ih0   [1024, 3072], K=512
    sgemm_nt<<<dim3(C3H / 128, (CB * CT) / 128, 1), 256>>>(p_emb, W_ih0, b_ih0, p_gi,
        CB * CT, C3H, CE, C3H, 0, 0, 0);
    // 3. GRU layer 0 (persistent)
    gru_layer_kernel<<<128, 256>>>(p_gi, W_hh0, b_hh0, p_h1);
    // 4. gi1 = h1 @ W_ih1^T + b_ih1    [1024, 3072], K=1024
    sgemm_nt<<<dim3(C3H / 128, (CB * CT) / 128, 1), 256>>>(p_h1, W_ih1, b_ih1, p_gi,
        CB * CT, C3H, CH, C3H, 0, 0, 0);
    // 5. GRU layer 1
    gru_layer_kernel<<<128, 256>>>(p_gi, W_hh1, b_hh1, p_rnn);
    // 6. attention memory projections
    sgemm_nt<<<dim3(CH / 128, (CB * CS) / 128, 1), 256>>>(s_output, att_s_w, att_s_b, p_ps,
        CB * CS, CH, CM, CH, 0, 0, 0);
    sgemm_nt<<<dim3(CH / 128, (CB * CU) / 128, 1), 256>>>(u_output, att_u_w, att_u_b, p_pu,
        CB * CU, CH, CM, CH, 0, 0, 0);
    sgemm_nt<<<dim3(CH / 128, (CB * CW) / 128, 1), 256>>>(w_output, att_w_w, att_w_b, p_pw,
        CB * CW, CH, CM2, CH, 0, 0, 0);
    // 7. raw scores
    attn_scores_kernel<<<(CB * CT * CS) / 8, 256>>>(p_rnn, p_ps, p_scs, CS);
    attn_scores_kernel<<<(CB * CT * CU) / 8, 256>>>(p_rnn, p_pu, p_scu, CU);
    sgemm_nt<<<dim3(CW / 128, CT / 128, CB), 256>>>(p_rnn, p_pw, nullptr, p_scw,
        CT, CW, CH, CW, (long)CT * CH, (long)CW * CH, (long)CT * CW);
    // 8. masked softmaxes + hierarchical combine + final softmax
    combine_kernel<<<CB * CT, 256>>>(s_len, u_len, w_len, seg, utt);
    // 9. context = suw @ w_output  (needs w_output^T per batch for NT gemm)
    transpose_w_kernel<<<dim3(CW / 32, CM2 / 32, CB), dim3(32, 8)>>>(w_output);
    sgemm_nt<<<dim3(CM2 / 128, CT / 128, CB), 256>>>(p_suw, p_wT, nullptr, p_feat,
        CT, CM2, CW, CF, (long)CT * CW, (long)CM2 * CW, (long)CT * CF);
    // 10. feat[:, 1024:2048] = rnn_out
    copy_rnn_kernel<<<(CB * CT * CH + 255) / 256, 256>>>();
    // 11. logits = feat @ out_w^T + out_b  -> d_out   [1024, 32000], K=2048
    sgemm_nt<<<dim3(CV / 128, (CB * CT) / 128, 1), 256>>>(p_feat, out_w, out_b, out,
        CB * CT, CV, CF, CV, 0, 0, 0);
    // 12. in-place log_softmax
    logsoftmax_kernel<<<CB * CT, 256>>>(out);
}